// round 17
// baseline (speedup 1.0000x reference)
#include <cuda_runtime.h>
#include <math.h>

// Problem constants (fixed shapes)
#define B_  4
#define C_  32
#define T_  48
#define N_  2000
#define E_  16000
#define BT_ (B_ * T_)   // 192

#define PTSB 256        // points per conv block
#define NBLK 8          // ceil(2000/256)
#define TSTRIDE 18      // transpose tile row stride (words)
#define CHALF 16        // channels per block (co-split)

typedef unsigned long long ull;

// ---------------------------------------------------------------------------
// Scratch (device globals)
// ---------------------------------------------------------------------------
__device__ float g_xw[BT_ * N_ * C_];     // h = relu(conv1), layout [g][n][c]
__device__ float g_gout[BT_ * C_ * N_];   // agg output z, layout [g][c][n]
__device__ int   g_srcb[E_];
__device__ int   g_dstb[E_];
__device__ int   g_off[N_ + 1];
__device__ int   g_csr_src[E_];
__device__ float g_csr_w[E_];
__device__ float g_invdeg[N_];
__device__ float g_w2p[32 * 3 * 32];      // folded w2' : [(c1*3+kt)*32 + co]
__device__ float g_bk[3 * 32];            // per-tap bias : [kt*32 + co]

// ---------------------------------------------------------------------------
// f32x2 helpers
// ---------------------------------------------------------------------------
__device__ __forceinline__ ull dup2(float x) {
    ull r;
    unsigned u = __float_as_uint(x);
    asm("mov.b64 %0, {%1, %1};" : "=l"(r) : "r"(u));
    return r;
}
__device__ __forceinline__ void ffma2(ull& acc, ull a, ull b) {
    asm("fma.rn.f32x2 %0, %1, %2, %0;" : "+l"(acc) : "l"(a), "l"(b));
}
__device__ __forceinline__ float2 unpack2(ull v) {
    unsigned lo, hi;
    asm("mov.b64 {%0, %1}, %2;" : "=r"(lo), "=r"(hi) : "l"(v));
    return make_float2(__uint_as_float(lo), __uint_as_float(hi));
}

// ---------------------------------------------------------------------------
// K1: conv1+relu, 2 temporal outputs per block, co-split (16 of 32 channels).
// POINT-PAIR accumulators: inputs load as natural f32x2 (zero dup movs);
// weights pre-duplicated into smem as f32x2 (dup paid once per block).
// Coalesced map: cog=tid&3, ptg=tid>>2 -> 8 point-groups/warp -> 128B LDG.
// CSR prep + weight folding fused in as one extra block (blockIdx.x==2*NBLK).
// acc[tt][pp][c]: f32x2 over point pair (nb+2pp, nb+2pp+1), channel lc0+c.
// ---------------------------------------------------------------------------
__global__ void __launch_bounds__(256, 3) k_conv1(
    const float* __restrict__ x,
    const void*  __restrict__ edges,
    const float* __restrict__ w1,
    const float* __restrict__ b1,
    const float* __restrict__ gcn_w,
    const float* __restrict__ gcn_b,
    const float* __restrict__ w2)
{
    __shared__ __align__(16) union U {
        float pool[PTSB * TSTRIDE];       // transpose tile [256][18]
        struct {
            int   cnt[2000];
            int   off[2000];
            float dinv[2000];
            int   wsum[8];
            int   is64;
        } prep;
    } u;
    __shared__ __align__(16) ull w1d[96 * CHALF];   // dup'd: [(ci*3+kt)*16 + lc]
    __shared__ __align__(16) ull b1d[CHALF];

    int tid = threadIdx.x;

    // ---------------- fused preprocessing block ----------------
    if (blockIdx.x == 2 * NBLK) {
        if (blockIdx.y != 0 || blockIdx.z != 0) return;

        if (tid == 0) {
            const int* q = (const int*)edges;
            int ok = 1;
            #pragma unroll 1
            for (int i = 0; i < 64; i++) {
                if (q[2 * i + 1] != 0) { ok = 0; break; }
            }
            u.prep.is64 = ok;
        }
        for (int i = tid; i < N_; i += 256) u.prep.cnt[i] = 0;
        __syncthreads();
        const int is64 = u.prep.is64;

        #pragma unroll 1
        for (int e = tid; e < E_; e += 256) {
            int s, d;
            if (is64) {
                const long long* p = (const long long*)edges;
                s = (int)p[e];
                d = (int)p[E_ + e];
            } else {
                const int* p = (const int*)edges;
                s = p[e];
                d = p[E_ + e];
            }
            g_srcb[e] = s;
            g_dstb[e] = d;
            atomicAdd(&u.prep.cnt[d], 1);
        }
        __syncthreads();

        // block scan over 2000 counts (8 per thread, 256 threads)
        int lane = tid & 31, wid = tid >> 5;
        int base = tid * 8;
        int c[8];
        int sum = 0;
        #pragma unroll
        for (int i = 0; i < 8; i++) {
            int idx = base + i;
            c[i] = (idx < N_) ? u.prep.cnt[idx] : 0;
            sum += c[i];
        }
        int incl = sum;
        #pragma unroll
        for (int o = 1; o < 32; o <<= 1) {
            int v = __shfl_up_sync(0xffffffffu, incl, o);
            if (lane >= o) incl += v;
        }
        if (lane == 31) u.prep.wsum[wid] = incl;
        __syncthreads();
        int woff = 0;
        #pragma unroll
        for (int w = 0; w < 8; w++) woff += (w < wid) ? u.prep.wsum[w] : 0;
        int run = woff + incl - sum;
        #pragma unroll
        for (int i = 0; i < 8; i++) {
            int idx = base + i;
            if (idx < N_) {
                u.prep.off[idx] = run;
                g_off[idx] = run;
                float deg = (float)c[i] + 1.0f;
                u.prep.dinv[idx] = rsqrtf(deg);
                g_invdeg[idx] = 1.0f / deg;
            }
            run += c[i];
        }
        if (tid == 0) g_off[N_] = E_;
        __syncthreads();
        for (int i = tid; i < N_; i += 256) u.prep.cnt[i] = 0;
        __syncthreads();

        #pragma unroll 1
        for (int e = tid; e < E_; e += 256) {
            int s = g_srcb[e];
            int d = g_dstb[e];
            int pos = atomicAdd(&u.prep.cnt[d], 1);
            int idx = u.prep.off[d] + pos;
            g_csr_src[idx] = s;
            g_csr_w[idx] = u.prep.dinv[s] * u.prep.dinv[d];
        }

        // weight folding: w2'[co,c1,kt] = sum_c2 w2[co,c2,kt]*gcn_w[c1,c2]
        #pragma unroll 1
        for (int i = tid; i < 32 * 3 * 32; i += 256) {
            int co = i & 31;
            int r  = i >> 5;        // r = c1*3 + kt
            int kt = r % 3;
            int c1 = r / 3;
            float s = 0.0f;
            #pragma unroll 8
            for (int c2 = 0; c2 < 32; c2++)
                s += w2[(co * 32 + c2) * 3 + kt] * gcn_w[c1 * 32 + c2];
            g_w2p[i] = s;
        }
        // per-tap bias: bk[kt,co] = sum_c2 w2[co,c2,kt]*gcn_b[c2]
        if (tid < 96) {
            int co = tid & 31;
            int kt = tid >> 5;
            float s = 0.0f;
            #pragma unroll 8
            for (int c2 = 0; c2 < 32; c2++)
                s += w2[(co * 32 + c2) * 3 + kt] * gcn_b[c2];
            g_bk[kt * 32 + co] = s;
        }
        return;
    }

    // ---------------- conv1 + relu (2 t's, 16 channels per block) ----------
    int ch0 = (blockIdx.x & 1) * CHALF;
    int nbk = blockIdx.x >> 1;

    for (int i = tid; i < 96 * CHALF; i += 256) {
        int lc = i & 15;
        int r = i >> 4;
        int kt = r % 3;
        int ci = r / 3;
        w1d[i] = dup2(w1[((ch0 + lc) * C_ + ci) * 3 + kt]);
    }
    if (tid < CHALF) b1d[tid] = dup2(b1[ch0 + tid]);
    __syncthreads();

    int cog = tid & 3;
    int ptg = tid >> 2;              // 0..63, 4 points each (8/warp -> 128B)
    int lc0 = cog * 4;               // local channel base (0,4,8,12)
    int n0  = nbk * PTSB;
    int nb  = n0 + ptg * 4;
    bool alive = (nb < N_);
    int t0 = blockIdx.y * 2;         // outputs t0, t0+1
    int b  = blockIdx.z;

    bool pv0 = (t0 > 0) && alive;
    bool pv1 = alive;
    bool pv3 = (t0 + 2 < T_) && alive;

    ull acc[2][2][4];
    #pragma unroll
    for (int c = 0; c < 4; c++) {
        ull bq = b1d[lc0 + c];
        #pragma unroll
        for (int tt = 0; tt < 2; tt++)
            #pragma unroll
            for (int pp = 0; pp < 2; pp++) acc[tt][pp][c] = bq;
    }

    const float* xrow = x + ((size_t)(b * C_ * T_) + (t0 - 1)) * N_ + nb;
    #pragma unroll 2
    for (int ci = 0; ci < 32; ci++) {
        const float* xr = xrow + ci * (T_ * N_);
        ulonglong2 in[4];
        if (pv0) in[0] = *(const ulonglong2*)(xr);          else { in[0].x = 0; in[0].y = 0; }
        if (pv1) in[1] = *(const ulonglong2*)(xr + N_);     else { in[1].x = 0; in[1].y = 0; }
        if (pv1) in[2] = *(const ulonglong2*)(xr + 2 * N_); else { in[2].x = 0; in[2].y = 0; }
        if (pv3) in[3] = *(const ulonglong2*)(xr + 3 * N_); else { in[3].x = 0; in[3].y = 0; }
        #pragma unroll
        for (int kt = 0; kt < 3; kt++) {
            const ulonglong2* wp = (const ulonglong2*)&w1d[(ci * 3 + kt) * CHALF + lc0];
            ulonglong2 wA = wp[0];      // wd[0], wd[1]
            ulonglong2 wB = wp[1];      // wd[2], wd[3]
            #pragma unroll
            for (int tt = 0; tt < 2; tt++) {
                int j = kt + tt;
                ffma2(acc[tt][0][0], in[j].x, wA.x);
                ffma2(acc[tt][0][1], in[j].x, wA.y);
                ffma2(acc[tt][0][2], in[j].x, wB.x);
                ffma2(acc[tt][0][3], in[j].x, wB.y);
                ffma2(acc[tt][1][0], in[j].y, wA.x);
                ffma2(acc[tt][1][1], in[j].y, wA.y);
                ffma2(acc[tt][1][2], in[j].y, wB.x);
                ffma2(acc[tt][1][3], in[j].y, wB.y);
            }
        }
    }

    // epilogue: per t -> relu -> transpose tile -> coalesced store (tile reused)
    float* xwt = u.pool;
    int pl = ptg * 4;
    int g0 = b * T_ + t0;
    int rows = min(PTSB, N_ - n0);
    int total = rows * CHALF;
    #pragma unroll
    for (int tt = 0; tt < 2; tt++) {
        #pragma unroll
        for (int pp = 0; pp < 2; pp++) {
            #pragma unroll
            for (int c = 0; c < 4; c++) {
                float2 v = unpack2(acc[tt][pp][c]);   // (point 2pp, point 2pp+1)
                xwt[(pl + 2 * pp)     * TSTRIDE + lc0 + c] = fmaxf(v.x, 0.0f);
                xwt[(pl + 2 * pp + 1) * TSTRIDE + lc0 + c] = fmaxf(v.y, 0.0f);
            }
        }
        __syncthreads();
        float* dst = g_xw + ((size_t)(g0 + tt) * N_ + n0) * C_ + ch0;
        for (int i = tid; i < total; i += 256) {
            int r = i >> 4, c = i & 15;
            dst[r * C_ + c] = xwt[r * TSTRIDE + c];
        }
        __syncthreads();
    }
}

// ---------------------------------------------------------------------------
// K2: GCN aggregation over h; 4 graphs per warp. z = aggH + invdeg*h.
// Writes g_gout transposed [g][c][n].
// ---------------------------------------------------------------------------
__global__ void __launch_bounds__(256) k_agg() {
    __shared__ __align__(16) float sbuf[4 * 256];   // [gg][lane*8+warp]
    int warp = threadIdx.x >> 5;
    int lane = threadIdx.x & 31;
    int n  = blockIdx.x * 8 + warp;
    int g0 = blockIdx.y * 4;

    int s0 = g_off[n];
    int s1 = g_off[n + 1];
    const float* __restrict__ xw0 = g_xw + (size_t)g0 * N_ * C_;
    const size_t GS = (size_t)N_ * C_;

    float acc[4] = {0.f, 0.f, 0.f, 0.f};
    int e = s0;
    for (; e + 1 < s1; e += 2) {
        int   sA = g_csr_src[e];
        int   sB = g_csr_src[e + 1];
        float wA = g_csr_w[e];
        float wB = g_csr_w[e + 1];
        float vA[4], vB[4];
        #pragma unroll
        for (int gg = 0; gg < 4; gg++) vA[gg] = __ldg(&xw0[gg * GS + sA * C_ + lane]);
        #pragma unroll
        for (int gg = 0; gg < 4; gg++) vB[gg] = __ldg(&xw0[gg * GS + sB * C_ + lane]);
        #pragma unroll
        for (int gg = 0; gg < 4; gg++) acc[gg] += wA * vA[gg] + wB * vB[gg];
    }
    if (e < s1) {
        int   sA = g_csr_src[e];
        float wA = g_csr_w[e];
        #pragma unroll
        for (int gg = 0; gg < 4; gg++) acc[gg] += wA * __ldg(&xw0[gg * GS + sA * C_ + lane]);
    }
    float idg = g_invdeg[n];
    #pragma unroll
    for (int gg = 0; gg < 4; gg++) {
        acc[gg] += idg * xw0[gg * GS + n * C_ + lane];
        sbuf[gg * 256 + lane * 8 + warp] = acc[gg];
    }
    __syncthreads();

    // transposed store: [g][c][n0..n0+7]
    int n0 = blockIdx.x * 8;
    #pragma unroll
    for (int r = 0; r < 4; r++) {
        int idx = r * 256 + threadIdx.x;
        int gg = idx >> 8;
        int c  = (idx >> 3) & 31;
        int j  = idx & 7;
        g_gout[((size_t)(g0 + gg) * C_ + c) * N_ + n0 + j] = sbuf[gg * 256 + c * 8 + j];
    }
}

// ---------------------------------------------------------------------------
// K3: conv2 with folded weights + per-tap bias, 2 temporal outputs per block,
// co-split, POINT-PAIR accumulators (zero dup movs in the hot loop; weights
// pre-dup'd in smem). Direct coalesced LDG from g_gout [g][c][n]; per-co
// float4 STG.128 output straight from accumulators.
// ---------------------------------------------------------------------------
__global__ void __launch_bounds__(256, 3) k_conv2(
    const float* __restrict__ b2,
    float* __restrict__ out)
{
    __shared__ __align__(16) ull w2d[96 * CHALF];   // dup'd folded weights
    __shared__ __align__(16) float bks[3 * CHALF];  // [kt*16 + lc]
    __shared__ __align__(16) float b2s[CHALF];

    int tid = threadIdx.x;
    int ch0 = (blockIdx.x & 1) * CHALF;
    int nbk = blockIdx.x >> 1;

    for (int i = tid; i < 96 * CHALF; i += 256) {
        int lc = i & 15;
        int r = i >> 4;                 // r = c1*3 + kt
        w2d[i] = dup2(g_w2p[r * 32 + ch0 + lc]);
    }
    if (tid < 3 * CHALF) {
        int kt = tid >> 4;
        int lc = tid & 15;
        bks[tid] = g_bk[kt * 32 + ch0 + lc];
    }
    if (tid < CHALF) b2s[tid] = b2[ch0 + tid];
    __syncthreads();

    int cog = tid & 3;
    int ptg = tid >> 2;
    int lc0 = cog * 4;
    int n0  = nbk * PTSB;
    int nb  = n0 + ptg * 4;
    bool alive = (nb < N_);
    int t0 = blockIdx.y * 2;
    int b  = blockIdx.z;

    bool tv0 = (t0 > 0);
    bool tv3 = (t0 + 2 < T_);
    bool pv0 = tv0 && alive;
    bool pv1 = alive;
    bool pv3 = tv3 && alive;

    ull acc[2][2][4];
    #pragma unroll
    for (int c = 0; c < 4; c++) {
        int lc = lc0 + c;
        // t = t0: taps kt=1,2 always valid; kt=0 iff t0>0
        float q0 = b2s[lc] + bks[16 + lc] + bks[32 + lc] + (tv0 ? bks[lc] : 0.0f);
        // t = t0+1: taps kt=0,1 always valid; kt=2 iff t0+2<T
        float q1 = b2s[lc] + bks[lc] + bks[16 + lc] + (tv3 ? bks[32 + lc] : 0.0f);
        ull d0 = dup2(q0), d1 = dup2(q1);
        #pragma unroll
        for (int pp = 0; pp < 2; pp++) {
            acc[0][pp][c] = d0;
            acc[1][pp][c] = d1;
        }
    }

    const float* grow = g_gout + ((size_t)(b * T_) + (t0 - 1)) * C_ * N_ + nb;
    #pragma unroll 2
    for (int ci = 0; ci < 32; ci++) {
        const float* gr = grow + (size_t)ci * N_;
        ulonglong2 in[4];
        if (pv0) in[0] = *(const ulonglong2*)(gr);                       else { in[0].x = 0; in[0].y = 0; }
        if (pv1) in[1] = *(const ulonglong2*)(gr + (size_t)C_ * N_);     else { in[1].x = 0; in[1].y = 0; }
        if (pv1) in[2] = *(const ulonglong2*)(gr + (size_t)2 * C_ * N_); else { in[2].x = 0; in[2].y = 0; }
        if (pv3) in[3] = *(const ulonglong2*)(gr + (size_t)3 * C_ * N_); else { in[3].x = 0; in[3].y = 0; }
        #pragma unroll
        for (int kt = 0; kt < 3; kt++) {
            const ulonglong2* wp = (const ulonglong2*)&w2d[(ci * 3 + kt) * CHALF + lc0];
            ulonglong2 wA = wp[0];
            ulonglong2 wB = wp[1];
            #pragma unroll
            for (int tt = 0; tt < 2; tt++) {
                int j = kt + tt;
                ffma2(acc[tt][0][0], in[j].x, wA.x);
                ffma2(acc[tt][0][1], in[j].x, wA.y);
                ffma2(acc[tt][0][2], in[j].x, wB.x);
                ffma2(acc[tt][0][3], in[j].x, wB.y);
                ffma2(acc[tt][1][0], in[j].y, wA.x);
                ffma2(acc[tt][1][1], in[j].y, wA.y);
                ffma2(acc[tt][1][2], in[j].y, wB.x);
                ffma2(acc[tt][1][3], in[j].y, wB.y);
            }
        }
    }

    if (alive) {
        #pragma unroll
        for (int tt = 0; tt < 2; tt++) {
            #pragma unroll
            for (int c = 0; c < 4; c++) {
                float2 lo = unpack2(acc[tt][0][c]);   // points nb+0, nb+1
                float2 hi = unpack2(acc[tt][1][c]);   // points nb+2, nb+3
                float4 v = make_float4(lo.x, lo.y, hi.x, hi.y);
                int co = ch0 + lc0 + c;
                *(float4*)(out + ((size_t)(b * C_ + co) * T_ + t0 + tt) * N_ + nb) = v;
            }
        }
    }
}

// ---------------------------------------------------------------------------
// Launcher
// ---------------------------------------------------------------------------
extern "C" void kernel_launch(void* const* d_in, const int* in_sizes, int n_in,
                              void* d_out, int out_size) {
    const float* x     = (const float*)d_in[0];
    const void*  edges = d_in[1];
    const float* w1    = (const float*)d_in[2];
    const float* b1    = (const float*)d_in[3];
    const float* gcn_w = (const float*)d_in[4];
    const float* gcn_b = (const float*)d_in[5];
    const float* w2    = (const float*)d_in[6];
    const float* b2    = (const float*)d_in[7];
    float* out = (float*)d_out;

    dim3 g1(2 * NBLK + 1, T_ / 2, B_);   // co-split x2; +1 block = prep+folding
    k_conv1<<<g1, 256>>>(x, edges, w1, b1, gcn_w, gcn_b, w2);

    dim3 ga(N_ / 8, BT_ / 4);
    k_agg<<<ga, 256>>>();

    dim3 g2(2 * NBLK, T_ / 2, B_);       // co-split x2
    k_conv2<<<g2, 256>>>(b2, out);
}